// round 1
// baseline (speedup 1.0000x reference)
#include <cuda_runtime.h>

// Problem constants (fixed by the reference setup)
#define BB    8
#define NMAX  128
#define HH    192
#define WW    256
#define INV_DOWN 0.125f

// Scratch (no allocations allowed in kernel_launch)
__device__ float g_err[BB * NMAX];
__device__ float g_valid[BB * NMAX];

// Antiderivative of the bilinear hat kernel, clipped to [-1, 1]
__device__ __forceinline__ float hatP(float u) {
    u = fminf(1.0f, fmaxf(-1.0f, u));
    return (u <= 0.0f) ? 0.5f * (u + 1.0f) * (u + 1.0f)
                       : 0.5f + u - 0.5f * u * u;
}

__global__ __launch_bounds__(128)
void count_kernel(const float* __restrict__ den,     // [B, 1, H, W]
                  const float* __restrict__ hboxes,  // [B, NMAX, 5]
                  const float* __restrict__ post)    // [B, NMAX, H, W]
{
    const int bn = blockIdx.x;          // 0 .. B*NMAX-1
    const int b  = bn / NMAX;
    const int t  = threadIdx.x;

    const float* box = hboxes + (size_t)bn * 5;
    const float x1 = __ldg(box + 0) * INV_DOWN;
    const float y1 = __ldg(box + 1) * INV_DOWN;
    const float x2 = __ldg(box + 2) * INV_DOWN;
    const float y2 = __ldg(box + 3) * INV_DOWN;
    const float lab = __ldg(box + 4);
    const float validf = (lab > 0.0f) ? 1.0f : 0.0f;

    // Support of the hat weights: i in (lo-1, hi+1). Pad by 1 cell each side;
    // extra entries evaluate to exactly 0 via the clipped antiderivative.
    const int ix0 = max(0, (int)floorf(x1) - 1);
    const int ix1 = min(WW - 1, (int)ceilf(x2) + 1);
    const int iy0 = max(0, (int)floorf(y1) - 1);
    const int iy1 = min(HH - 1, (int)ceilf(y2) + 1);
    const int nx = ix1 - ix0 + 1;   // <= ~24
    const int ny = iy1 - iy0 + 1;   // <= ~24

    __shared__ float wx[32];
    __shared__ float wy[32];
    if (t < nx) {
        float i = (float)(ix0 + t);
        wx[t] = hatP(x2 - i) - hatP(x1 - i);
    }
    if (t < ny) {
        float i = (float)(iy0 + t);
        wy[t] = hatP(y2 - i) - hatP(y1 - i);
    }
    __syncthreads();

    const float* denB  = den  + (size_t)b  * HH * WW;
    const float* postN = post + (size_t)bn * HH * WW;

    const int total = nx * ny;
    float acc = 0.0f;
    for (int k = t; k < total; k += 128) {
        const int jy = k / nx;
        const int jx = k - jy * nx;
        const int y = iy0 + jy;
        const int x = ix0 + jx;
        const int idx = y * WW + x;
        acc += wy[jy] * wx[jx] * __ldg(denB + idx) * __ldg(postN + idx);
    }

    // Block reduction: 4 warps
    #pragma unroll
    for (int o = 16; o > 0; o >>= 1)
        acc += __shfl_down_sync(0xffffffffu, acc, o);

    __shared__ float warpsum[4];
    if ((t & 31) == 0) warpsum[t >> 5] = acc;
    __syncthreads();
    if (t == 0) {
        float count = warpsum[0] + warpsum[1] + warpsum[2] + warpsum[3];
        g_err[bn]   = fabsf(count - 1.0f) * validf;
        g_valid[bn] = validf;
    }
}

__global__ __launch_bounds__(256)
void finalize_kernel(float* __restrict__ out)
{
    const int wid  = threadIdx.x >> 5;   // warp id -> image b
    const int lane = threadIdx.x & 31;
    __shared__ float s[BB];

    if (wid < BB) {
        float e = 0.0f, v = 0.0f;
        #pragma unroll
        for (int n = lane; n < NMAX; n += 32) {
            e += g_err[wid * NMAX + n];
            v += g_valid[wid * NMAX + n];
        }
        #pragma unroll
        for (int o = 16; o > 0; o >>= 1) {
            e += __shfl_down_sync(0xffffffffu, e, o);
            v += __shfl_down_sync(0xffffffffu, v, o);
        }
        if (lane == 0)
            s[wid] = (v > 0.0f) ? (e / fmaxf(v, 1.0f)) : 0.0f;
    }
    __syncthreads();
    if (threadIdx.x == 0) {
        float tot = 0.0f;
        #pragma unroll
        for (int b = 0; b < BB; b++) tot += s[b];
        out[0] = tot;
    }
}

extern "C" void kernel_launch(void* const* d_in, const int* in_sizes, int n_in,
                              void* d_out, int out_size)
{
    // metadata order: cls(0), reg(1), off(2), den(3), fboxes(4), hboxes(5),
    //                 ctr_masks(6), post_probs(7)
    const float* den    = (const float*)d_in[3];
    const float* hboxes = (const float*)d_in[5];
    const float* post   = (const float*)d_in[7];
    float* out = (float*)d_out;

    count_kernel<<<BB * NMAX, 128>>>(den, hboxes, post);
    finalize_kernel<<<1, 256>>>(out);
}